// round 13
// baseline (speedup 1.0000x reference)
#include <cuda_runtime.h>
#include <cuda_fp16.h>
#include <math.h>

#define S    129
#define SS   (S*S)            // 16641
#define SV   (S*S*S)          // 2146689
#define P    131              // padded side (1-voxel zero border)
#define PP   (P*P)            // 17161
#define PV   (P*P*P)          // 2248091
#define L    224
#define LL2  (L*L)            // 50176
#define LV   (L*L*L)          // 11239424
#define OFF  48               // L/2 - S/2
#define CABS 0.2f

// Scratch (allocation-free rule: __device__ globals; zero-initialized at load).
// Padded density, x-pair packed: element [z][y][x] = (v[x], v[x+1]) fp32.
__device__ float2 g_pd2[PV];
// Transmittance volumes, z-pair packed: element [col][z] = (v[z], v[z+1]) fp16.
__device__ __half2 g_upb[2][LV];

struct Mat3 { float m[9]; };

// ---------- trilinear over x-pair-packed padded density ----------
__device__ __forceinline__ float triS_f2(const float2* __restrict__ pd,
                                         float x, float y, float z) {
    float fx = floorf(x), fy = floorf(y), fz = floorf(z);
    int ib = ((int)fz + 1) * PP + ((int)fy + 1) * P + ((int)fx + 1);
    float wx = x - fx, wy = y - fy, wz = z - fz;
    const float2* p = pd + ib;
    float2 q00 = __ldg(p);               // (z0,   y0)
    float2 q01 = __ldg(p + P);           // (z0,   y0+1)
    float2 q10 = __ldg(p + PP);          // (z0+1, y0)
    float2 q11 = __ldg(p + PP + P);      // (z0+1, y0+1)
    float c00 = q00.x + wx * (q00.y - q00.x);
    float c01 = q01.x + wx * (q01.y - q01.x);
    float c10 = q10.x + wx * (q10.y - q10.x);
    float c11 = q11.x + wx * (q11.y - q11.x);
    float c0  = c00 + wy * (c01 - c00);
    float c1  = c10 + wy * (c11 - c10);
    return c0 + wz * (c1 - c0);
}

// ---------- trilinear over z-pair-packed up volume ([y][x][z], half2) ----------
__device__ __forceinline__ float triLT_h2(const __half2* __restrict__ v,
                                          float x, float y, float z) {
    float fx = floorf(x), fy = floorf(y), fz = floorf(z);
    int ib = ((int)fy * L + (int)fx) * L + (int)fz;
    float wx = x - fx, wy = y - fy, wz = z - fz;
    const __half2* p = v + ib;
    float2 q00 = __half22float2(__ldg(p));             // (x0,   y0)
    float2 q01 = __half22float2(__ldg(p + L));         // (x0+1, y0)
    float2 q10 = __half22float2(__ldg(p + LL2));       // (x0,   y0+1)
    float2 q11 = __half22float2(__ldg(p + LL2 + L));   // (x0+1, y0+1)
    float m00 = q00.x + wz * (q00.y - q00.x);
    float m01 = q01.x + wz * (q01.y - q01.x);
    float m10 = q10.x + wz * (q10.y - q10.x);
    float m11 = q11.x + wz * (q11.y - q11.x);
    float m0 = m00 + wx * (m01 - m00);
    float m1 = m10 + wx * (m11 - m10);
    return m0 + wy * (m1 - m0);
}

// warp-wide suffix (reverse inclusive) scan: s_l = sum_{m>=l} v_m
__device__ __forceinline__ float warp_suffix_scan(float s, int lane) {
    #pragma unroll
    for (int off = 1; off < 32; off <<= 1) {
        float t = __shfl_down_sync(0xffffffffu, s, off);
        if (lane < 32 - off) s += t;
    }
    return s;
}

// ---------- kernel P: build x-pair-packed bordered density ----------
__global__ void __launch_bounds__(256) kP(const float* __restrict__ d) {
    int i0 = (blockIdx.x * 256 + threadIdx.x) * 4;
    #pragma unroll
    for (int k = 0; k < 4; ++k) {
        int i = i0 + k;
        if (i < SV) {
            int z = i / SS;
            int r = i - z * SS;
            int y = r / S;
            int x = r - y * S;
            float v  = __ldg(d + i);
            float vn = (x + 1 < S) ? __ldg(d + i + 1) : 0.f;
            int base = (z + 1) * PP + (y + 1) * P;
            g_pd2[base + x + 1] = make_float2(v, vn);
            if (x == 0) g_pd2[base] = make_float2(0.f, v);   // left-border pair
        }
    }
}

// ---------- kernel A: rotate + suffix-cumsum + exp, one WARP per column ----------
__global__ void __launch_bounds__(128) kA(Mat3 R, int which) {
    int warp = threadIdx.x >> 5, lane = threadIdx.x & 31;
    int t = blockIdx.x * 4 + warp;               // column id, exact (12544*4 = L^2)
    __half2* __restrict__ up = g_upb[which];
    int x = t % L, y = t / L;
    float bx = -1.f + 2.f * (float)x / 223.f;
    float by = -1.f + 2.f * (float)y / 223.f;
    float A0 = 111.5f * (R.m[0] * bx + R.m[1] * by + 1.f - R.m[2]) - (float)OFF;
    float A1 = 111.5f * (R.m[3] * bx + R.m[4] * by + 1.f - R.m[5]) - (float)OFF;
    float A2 = 111.5f * (R.m[6] * bx + R.m[7] * by + 1.f - R.m[8]) - (float)OFF;
    float D0 = R.m[2], D1 = R.m[5], D2 = R.m[8];

    // slab intersection vs expanded bounds (-3, S+2); warp-uniform.
    const float lob = -3.f, hib = (float)S + 2.f;
    float t0 = 0.f, t1 = 223.f;
    {
        float A[3] = {A0, A1, A2}, D[3] = {D0, D1, D2};
        #pragma unroll
        for (int k = 0; k < 3; ++k) {
            if (fabsf(D[k]) < 1e-6f) {
                if (A[k] <= lob || A[k] >= hib) t1 = -1.e9f;
            } else {
                float u = __fdividef(lob - A[k], D[k]);
                float v = __fdividef(hib - A[k], D[k]);
                t0 = fmaxf(t0, fminf(u, v));
                t1 = fminf(t1, fmaxf(u, v));
            }
        }
    }
    if (t1 < t0) return;                         // column never touched by kBC
    int c0 = max(0, (int)floorf((t0 - 3.f) * 0.03125f));
    int c1 = min(6, (int)floorf((t1 + 3.f) * 0.03125f));

    float carry = 0.f;
    float prev_e = 1.f;                          // value at z = 32*c1 + 32
    __half2* __restrict__ col = up + (size_t)t * L;
    for (int cc = c1; cc >= c0; --cc) {          // march high z -> low z
        int zb = cc * 32;
        float zf = (float)(zb + lane);
        float px = fmaf(zf, D0, A0);
        float py = fmaf(zf, D1, A1);
        float pz = fmaf(zf, D2, A2);
        bool inb = (px > -1.f) && (px < (float)S) &&
                   (py > -1.f) && (py < (float)S) &&
                   (pz > -1.f) && (pz < (float)S);
        unsigned b = __ballot_sync(0xffffffffu, inb);
        float e;
        if (b == 0) {
            e = __expf(-CABS * carry);
        } else {
            float dv = inb ? triS_f2(g_pd2, px, py, pz) : 0.f;
            float s = warp_suffix_scan(dv, lane);
            e = __expf(-CABS * (carry + s));
            carry += __shfl_sync(0xffffffffu, s, 0);
        }
        float e_next = __shfl_down_sync(0xffffffffu, e, 1);
        if (lane == 31) e_next = prev_e;
        col[zb + lane] = __floats2half2_rn(e, e_next);
        prev_e = __shfl_sync(0xffffffffu, e, 0);
    }
}

// ---------- kernel BC: back-rotate both lights + composite, one WARP per pixel ----------
// Two-phase: phase 1 issues ALL chunks' gathers (MLP ~40, data-independent);
// phase 2 runs the serial scan/exp/accumulate chain with no memory waits.
__global__ void __launch_bounds__(128) kBC(const float* __restrict__ d,
                                           Mat3 R0, Mat3 R1,
                                           float* __restrict__ out) {
    __shared__ float sd[160 * 4];                // sd[(z+31)*4 + pixel], z in [-31,128]
    int tid = threadIdx.x;
    int warp = tid >> 5, lane = tid & 31;
    int t0 = blockIdx.x * 4;
    #pragma unroll
    for (int k = tid; k < 160 * 4; k += 128) sd[k] = 0.f;
    __syncthreads();
    for (int k = tid; k < S * 4; k += 128) {     // coalesced staging of d columns
        int z = k >> 2, j = k & 3;
        int t = t0 + j;
        if (t < SS) sd[(z + 31) * 4 + j] = __ldg(d + (size_t)z * SS + t);
    }
    __syncthreads();

    int t = t0 + warp;                           // this warp's pixel
    int x = t % S, y = t / S;
    const __half2* __restrict__ up0 = g_upb[0];
    const __half2* __restrict__ up1 = g_upb[1];
    float bx = -1.f + 2.f * (float)(x + OFF) / 223.f;
    float by = -1.f + 2.f * (float)(y + OFF) / 223.f;
    float bz0 = -1.f + 2.f * (float)OFF / 223.f;
    float B00 = 111.5f * (R0.m[0] * bx + R0.m[3] * by + R0.m[6] * bz0 + 1.f);
    float B01 = 111.5f * (R0.m[1] * bx + R0.m[4] * by + R0.m[7] * bz0 + 1.f);
    float B02 = 111.5f * (R0.m[2] * bx + R0.m[5] * by + R0.m[8] * bz0 + 1.f);
    float B10 = 111.5f * (R1.m[0] * bx + R1.m[3] * by + R1.m[6] * bz0 + 1.f);
    float B11 = 111.5f * (R1.m[1] * bx + R1.m[4] * by + R1.m[7] * bz0 + 1.f);
    float B12 = 111.5f * (R1.m[2] * bx + R1.m[5] * by + R1.m[8] * bz0 + 1.f);
    const float c227 = 227.f / 255.f, c69 = 69.f / 255.f, c25 = 25.f / 255.f, c66 = 66.f / 255.f;

    // ---- phase 1: all gathers / light-field samples, fully independent ----
    float dvv[5], cb0[5], cb1[5], cb2[5];
    #pragma unroll
    for (int c = 0; c < 5; ++c) {
        int z = (97 - 32 * c) + lane;            // bases 97,65,33,1,-31 cover 0..128
        dvv[c] = sd[(z + 31) * 4 + warp];        // 0 for z<0 / tail pixels
        float s0 = 0.f, s1 = 0.f;
        if (z >= 0) {
            float zf = (float)z;
            s0 = triLT_h2(up0, fmaf(zf, R0.m[6], B00),
                               fmaf(zf, R0.m[7], B01),
                               fmaf(zf, R0.m[8], B02));
            s1 = triLT_h2(up1, fmaf(zf, R1.m[6], B10),
                               fmaf(zf, R1.m[7], B11),
                               fmaf(zf, R1.m[8], B12));
        }
        cb0[c] = s0        + s1 * c227;
        cb1[c] = s0 * c69  + s1;
        cb2[c] = s0 * c25  + s1 * c66;
    }

    // ---- phase 2: serial scan / transmittance / accumulate (no memory) ----
    float carry = 0.f, a0 = 0.f, a1 = 0.f, a2 = 0.f;
    #pragma unroll
    for (int c = 0; c < 5; ++c) {
        float s = warp_suffix_scan(dvv[c], lane);
        float tr = __expf(-CABS * (carry + s));
        float w = dvv[c] * tr;
        a0 = fmaf(w, cb0[c], a0);
        a1 = fmaf(w, cb1[c], a1);
        a2 = fmaf(w, cb2[c], a2);
        carry += __shfl_sync(0xffffffffu, s, 0);
    }
    #pragma unroll
    for (int off = 16; off; off >>= 1) {
        a0 += __shfl_xor_sync(0xffffffffu, a0, off);
        a1 += __shfl_xor_sync(0xffffffffu, a1, off);
        a2 += __shfl_xor_sync(0xffffffffu, a2, off);
    }
    if (lane == 0 && t < SS) {
        out[t]          = fminf(fmaxf(CABS * a0, 0.f), 1.f);
        out[SS + t]     = fminf(fmaxf(CABS * a1, 0.f), 1.f);
        out[2 * SS + t] = fminf(fmaxf(CABS * a2, 0.f), 1.f);
    }
}

// ---------- host ----------

static void light_matrix(double lx, double ly, double lz, Mat3* Rf) {
    double n = sqrt(lx * lx + ly * ly + lz * lz);
    double ldx = lx / n, ldy = ly / n, ldz = lz / n;
    double yw = -asin(ldx);
    if (ldz < 0) yw = -M_PI - yw;
    double p = asin(ldy);
    double cy = cos(yw), sy = sin(yw), cp = cos(p), sp = sin(p);
    // R = Ry @ Rp
    double R[9] = { cy,  sy * sp,  sy * cp,
                    0.0, cp,      -sp,
                   -sy,  cy * sp,  cy * cp };
    for (int i = 0; i < 9; i++) Rf->m[i] = (float)R[i];
}

extern "C" void kernel_launch(void* const* d_in, const int* in_sizes, int n_in,
                              void* d_out, int out_size) {
    const float* d = (const float*)d_in[0];
    float* out = (float*)d_out;

    Mat3 R0, R1;
    light_matrix(2.0, 1.0, 1.0, &R0);
    light_matrix(-1.0, 0.5, 0.0, &R1);

    kP<<<(SV + 1023) / 1024, 256>>>(d);
    kA<<<LL2 / 4, 128>>>(R0, 0);
    kA<<<LL2 / 4, 128>>>(R1, 1);
    kBC<<<(SS + 3) / 4, 128>>>(d, R0, R1, out);
}

// round 15
// speedup vs baseline: 1.0035x; 1.0035x over previous
#include <cuda_runtime.h>
#include <cuda_fp16.h>
#include <math.h>

#define S    129
#define SS   (S*S)            // 16641
#define SV   (S*S*S)          // 2146689
#define P    131              // padded side (1-voxel zero border)
#define PP   (P*P)            // 17161
#define PV   (P*P*P)          // 2248091
#define L    224
#define LL2  (L*L)            // 50176
#define LV   (L*L*L)          // 11239424
#define OFF  48               // L/2 - S/2
#define CABS 0.2f

// Scratch (allocation-free rule: __device__ globals; zero-initialized at load).
// Padded density, x-pair packed: element [z][y][x] = (v[x], v[x+1]) fp32.
__device__ float2 g_pd2[PV];
// Transmittance volumes, z-pair packed: element [col][z] = (v[z], v[z+1]) fp16.
__device__ __half2 g_upb[2][LV];

struct Mat3 { float m[9]; };

// ---------- trilinear over x-pair-packed padded density ----------
__device__ __forceinline__ float triS_f2(const float2* __restrict__ pd,
                                         float x, float y, float z) {
    float fx = floorf(x), fy = floorf(y), fz = floorf(z);
    int ib = ((int)fz + 1) * PP + ((int)fy + 1) * P + ((int)fx + 1);
    float wx = x - fx, wy = y - fy, wz = z - fz;
    const float2* p = pd + ib;
    float2 q00 = __ldg(p);               // (z0,   y0)
    float2 q01 = __ldg(p + P);           // (z0,   y0+1)
    float2 q10 = __ldg(p + PP);          // (z0+1, y0)
    float2 q11 = __ldg(p + PP + P);      // (z0+1, y0+1)
    float c00 = q00.x + wx * (q00.y - q00.x);
    float c01 = q01.x + wx * (q01.y - q01.x);
    float c10 = q10.x + wx * (q10.y - q10.x);
    float c11 = q11.x + wx * (q11.y - q11.x);
    float c0  = c00 + wy * (c01 - c00);
    float c1  = c10 + wy * (c11 - c10);
    return c0 + wz * (c1 - c0);
}

// ---------- trilinear over z-pair-packed up volume ([y][x][z], half2) ----------
__device__ __forceinline__ float triLT_h2(const __half2* __restrict__ v,
                                          float x, float y, float z) {
    float fx = floorf(x), fy = floorf(y), fz = floorf(z);
    int ib = ((int)fy * L + (int)fx) * L + (int)fz;
    float wx = x - fx, wy = y - fy, wz = z - fz;
    const __half2* p = v + ib;
    float2 q00 = __half22float2(__ldg(p));             // (x0,   y0)
    float2 q01 = __half22float2(__ldg(p + L));         // (x0+1, y0)
    float2 q10 = __half22float2(__ldg(p + LL2));       // (x0,   y0+1)
    float2 q11 = __half22float2(__ldg(p + LL2 + L));   // (x0+1, y0+1)
    float m00 = q00.x + wz * (q00.y - q00.x);
    float m01 = q01.x + wz * (q01.y - q01.x);
    float m10 = q10.x + wz * (q10.y - q10.x);
    float m11 = q11.x + wz * (q11.y - q11.x);
    float m0 = m00 + wx * (m01 - m00);
    float m1 = m10 + wx * (m11 - m10);
    return m0 + wy * (m1 - m0);
}

// warp-wide suffix (reverse inclusive) scan: s_l = sum_{m>=l} v_m
__device__ __forceinline__ float warp_suffix_scan(float s, int lane) {
    #pragma unroll
    for (int off = 1; off < 32; off <<= 1) {
        float t = __shfl_down_sync(0xffffffffu, s, off);
        if (lane < 32 - off) s += t;
    }
    return s;
}

// ---------- kernel P: build x-pair-packed bordered density ----------
// 8 pairs per thread; 9 loads serve 8 pairs (vn shared with next element).
__global__ void __launch_bounds__(256) kP(const float* __restrict__ d) {
    int i0 = (blockIdx.x * 256 + threadIdx.x) * 8;
    if (i0 >= SV) return;
    float v[9];
    #pragma unroll
    for (int k = 0; k < 9; ++k) {
        int i = i0 + k;
        v[k] = (i < SV) ? __ldg(d + i) : 0.f;
    }
    #pragma unroll
    for (int k = 0; k < 8; ++k) {
        int i = i0 + k;
        if (i < SV) {
            int z = i / SS;
            int r = i - z * SS;
            int y = r / S;
            int x = r - y * S;
            float vn = (x + 1 < S) ? v[k + 1] : 0.f;   // 0 across row boundary
            int base = (z + 1) * PP + (y + 1) * P;
            g_pd2[base + x + 1] = make_float2(v[k], vn);
            if (x == 0) g_pd2[base] = make_float2(0.f, v[k]);   // left-border pair
        }
    }
}

// ---------- kernel A: rotate + suffix-cumsum + exp, one WARP per column ----------
// blockIdx.y selects the light (both lights in one launch: halves wave tail).
// Slab-culled; writes (e[z], e[z+1]) pairs; boundary above topmost chunk = 1.
__global__ void __launch_bounds__(128) kA(Mat3 R0, Mat3 R1) {
    int warp = threadIdx.x >> 5, lane = threadIdx.x & 31;
    int t = blockIdx.x * 4 + warp;               // column id, exact (12544*4 = L^2)
    const Mat3 R = blockIdx.y ? R1 : R0;
    __half2* __restrict__ up = g_upb[blockIdx.y];
    int x = t % L, y = t / L;
    float bx = -1.f + 2.f * (float)x / 223.f;
    float by = -1.f + 2.f * (float)y / 223.f;
    float A0 = 111.5f * (R.m[0] * bx + R.m[1] * by + 1.f - R.m[2]) - (float)OFF;
    float A1 = 111.5f * (R.m[3] * bx + R.m[4] * by + 1.f - R.m[5]) - (float)OFF;
    float A2 = 111.5f * (R.m[6] * bx + R.m[7] * by + 1.f - R.m[8]) - (float)OFF;
    float D0 = R.m[2], D1 = R.m[5], D2 = R.m[8];

    // slab intersection vs expanded bounds (-3, S+2); warp-uniform.
    const float lob = -3.f, hib = (float)S + 2.f;
    float t0 = 0.f, t1 = 223.f;
    {
        float A[3] = {A0, A1, A2}, D[3] = {D0, D1, D2};
        #pragma unroll
        for (int k = 0; k < 3; ++k) {
            if (fabsf(D[k]) < 1e-6f) {
                if (A[k] <= lob || A[k] >= hib) t1 = -1.e9f;
            } else {
                float u = __fdividef(lob - A[k], D[k]);
                float v = __fdividef(hib - A[k], D[k]);
                t0 = fmaxf(t0, fminf(u, v));
                t1 = fminf(t1, fmaxf(u, v));
            }
        }
    }
    if (t1 < t0) return;                         // column never touched by kBC
    int c0 = max(0, (int)floorf((t0 - 3.f) * 0.03125f));
    int c1 = min(6, (int)floorf((t1 + 3.f) * 0.03125f));

    float carry = 0.f;
    float prev_e = 1.f;                          // value at z = 32*c1 + 32
    __half2* __restrict__ col = up + (size_t)t * L;
    for (int cc = c1; cc >= c0; --cc) {          // march high z -> low z
        int zb = cc * 32;
        float zf = (float)(zb + lane);
        float px = fmaf(zf, D0, A0);
        float py = fmaf(zf, D1, A1);
        float pz = fmaf(zf, D2, A2);
        bool inb = (px > -1.f) && (px < (float)S) &&
                   (py > -1.f) && (py < (float)S) &&
                   (pz > -1.f) && (pz < (float)S);
        unsigned b = __ballot_sync(0xffffffffu, inb);
        float e;
        if (b == 0) {
            e = __expf(-CABS * carry);
        } else {
            float dv = inb ? triS_f2(g_pd2, px, py, pz) : 0.f;
            float s = warp_suffix_scan(dv, lane);
            e = __expf(-CABS * (carry + s));
            carry += __shfl_sync(0xffffffffu, s, 0);
        }
        float e_next = __shfl_down_sync(0xffffffffu, e, 1);
        if (lane == 31) e_next = prev_e;
        col[zb + lane] = __floats2half2_rn(e, e_next);
        prev_e = __shfl_sync(0xffffffffu, e, 0);
    }
}

// ---------- kernel BC: back-rotate both lights + composite, one WARP per pixel ----------
__global__ void __launch_bounds__(128) kBC(const float* __restrict__ d,
                                           Mat3 R0, Mat3 R1,
                                           float* __restrict__ out) {
    __shared__ float sd[160 * 4];                // sd[(z+31)*4 + pixel], z in [-31,128]
    int tid = threadIdx.x;
    int warp = tid >> 5, lane = tid & 31;
    int t0 = blockIdx.x * 4;
    #pragma unroll
    for (int k = tid; k < 160 * 4; k += 128) sd[k] = 0.f;
    __syncthreads();
    for (int k = tid; k < S * 4; k += 128) {     // coalesced staging of d columns
        int z = k >> 2, j = k & 3;
        int t = t0 + j;
        if (t < SS) sd[(z + 31) * 4 + j] = __ldg(d + (size_t)z * SS + t);
    }
    __syncthreads();

    int t = t0 + warp;                           // this warp's pixel
    int x = t % S, y = t / S;
    const __half2* __restrict__ up0 = g_upb[0];
    const __half2* __restrict__ up1 = g_upb[1];
    float bx = -1.f + 2.f * (float)(x + OFF) / 223.f;
    float by = -1.f + 2.f * (float)(y + OFF) / 223.f;
    float bz0 = -1.f + 2.f * (float)OFF / 223.f;
    float B00 = 111.5f * (R0.m[0] * bx + R0.m[3] * by + R0.m[6] * bz0 + 1.f);
    float B01 = 111.5f * (R0.m[1] * bx + R0.m[4] * by + R0.m[7] * bz0 + 1.f);
    float B02 = 111.5f * (R0.m[2] * bx + R0.m[5] * by + R0.m[8] * bz0 + 1.f);
    float B10 = 111.5f * (R1.m[0] * bx + R1.m[3] * by + R1.m[6] * bz0 + 1.f);
    float B11 = 111.5f * (R1.m[1] * bx + R1.m[4] * by + R1.m[7] * bz0 + 1.f);
    float B12 = 111.5f * (R1.m[2] * bx + R1.m[5] * by + R1.m[8] * bz0 + 1.f);
    float carry = 0.f, a0 = 0.f, a1 = 0.f, a2 = 0.f;
    const float c227 = 227.f / 255.f, c69 = 69.f / 255.f, c25 = 25.f / 255.f, c66 = 66.f / 255.f;
    #pragma unroll
    for (int c = 0; c < 5; ++c) {
        int z = (97 - 32 * c) + lane;            // bases 97,65,33,1,-31 cover 0..128
        float dv = sd[(z + 31) * 4 + warp];      // 0 for z<0 / tail pixels
        float comb0 = 0.f, comb1 = 0.f, comb2 = 0.f;
        if (z >= 0) {
            float zf = (float)z;
            float s0 = triLT_h2(up0, fmaf(zf, R0.m[6], B00),
                                     fmaf(zf, R0.m[7], B01),
                                     fmaf(zf, R0.m[8], B02));
            float s1 = triLT_h2(up1, fmaf(zf, R1.m[6], B10),
                                     fmaf(zf, R1.m[7], B11),
                                     fmaf(zf, R1.m[8], B12));
            comb0 = s0        + s1 * c227;
            comb1 = s0 * c69  + s1;
            comb2 = s0 * c25  + s1 * c66;
        }
        float s = warp_suffix_scan(dv, lane);
        float tr = __expf(-CABS * (carry + s));
        float w = dv * tr;
        a0 = fmaf(w, comb0, a0);
        a1 = fmaf(w, comb1, a1);
        a2 = fmaf(w, comb2, a2);
        carry += __shfl_sync(0xffffffffu, s, 0);
    }
    #pragma unroll
    for (int off = 16; off; off >>= 1) {
        a0 += __shfl_xor_sync(0xffffffffu, a0, off);
        a1 += __shfl_xor_sync(0xffffffffu, a1, off);
        a2 += __shfl_xor_sync(0xffffffffu, a2, off);
    }
    if (lane == 0 && t < SS) {
        out[t]          = fminf(fmaxf(CABS * a0, 0.f), 1.f);
        out[SS + t]     = fminf(fmaxf(CABS * a1, 0.f), 1.f);
        out[2 * SS + t] = fminf(fmaxf(CABS * a2, 0.f), 1.f);
    }
}

// ---------- host ----------

static void light_matrix(double lx, double ly, double lz, Mat3* Rf) {
    double n = sqrt(lx * lx + ly * ly + lz * lz);
    double ldx = lx / n, ldy = ly / n, ldz = lz / n;
    double yw = -asin(ldx);
    if (ldz < 0) yw = -M_PI - yw;
    double p = asin(ldy);
    double cy = cos(yw), sy = sin(yw), cp = cos(p), sp = sin(p);
    // R = Ry @ Rp
    double R[9] = { cy,  sy * sp,  sy * cp,
                    0.0, cp,      -sp,
                   -sy,  cy * sp,  cy * cp };
    for (int i = 0; i < 9; i++) Rf->m[i] = (float)R[i];
}

extern "C" void kernel_launch(void* const* d_in, const int* in_sizes, int n_in,
                              void* d_out, int out_size) {
    const float* d = (const float*)d_in[0];
    float* out = (float*)d_out;

    Mat3 R0, R1;
    light_matrix(2.0, 1.0, 1.0, &R0);
    light_matrix(-1.0, 0.5, 0.0, &R1);

    kP<<<(SV + 2047) / 2048, 256>>>(d);
    dim3 gridA(LL2 / 4, 2, 1);                   // both lights in one launch
    kA<<<gridA, 128>>>(R0, R1);
    kBC<<<(SS + 3) / 4, 128>>>(d, R0, R1, out);
}

// round 16
// speedup vs baseline: 1.0291x; 1.0255x over previous
#include <cuda_runtime.h>
#include <cuda_fp16.h>
#include <math.h>

#define S    129
#define SS   (S*S)            // 16641
#define SV   (S*S*S)          // 2146689
#define P    131              // padded side (1-voxel zero border)
#define PP   (P*P)            // 17161
#define PV   (P*P*P)          // 2248091
#define L    224
#define LL2  (L*L)            // 50176
#define LV   (L*L*L)          // 11239424
#define OFF  48               // L/2 - S/2
#define CABS 0.2f

// Scratch (allocation-free rule: __device__ globals; zero-initialized at load).
// Padded density, x-pair packed: element [z][y][x] = (v[x], v[x+1]) fp32.
__device__ float2 g_pd2[PV];
// Transmittance volumes, z-pair packed: element [col][z] = (v[z], v[z+1]) fp16.
__device__ __half2 g_upb[2][LV];

struct Mat3 { float m[9]; };

// ---------- trilinear over x-pair-packed padded density ----------
__device__ __forceinline__ float triS_f2(const float2* __restrict__ pd,
                                         float x, float y, float z) {
    float fx = floorf(x), fy = floorf(y), fz = floorf(z);
    int ib = ((int)fz + 1) * PP + ((int)fy + 1) * P + ((int)fx + 1);
    float wx = x - fx, wy = y - fy, wz = z - fz;
    const float2* p = pd + ib;
    float2 q00 = __ldg(p);               // (z0,   y0)
    float2 q01 = __ldg(p + P);           // (z0,   y0+1)
    float2 q10 = __ldg(p + PP);          // (z0+1, y0)
    float2 q11 = __ldg(p + PP + P);      // (z0+1, y0+1)
    float c00 = q00.x + wx * (q00.y - q00.x);
    float c01 = q01.x + wx * (q01.y - q01.x);
    float c10 = q10.x + wx * (q10.y - q10.x);
    float c11 = q11.x + wx * (q11.y - q11.x);
    float c0  = c00 + wy * (c01 - c00);
    float c1  = c10 + wy * (c11 - c10);
    return c0 + wz * (c1 - c0);
}

// ---------- trilinear over z-pair-packed up volume ([y][x][z], half2) ----------
__device__ __forceinline__ float triLT_h2(const __half2* __restrict__ v,
                                          float x, float y, float z) {
    float fx = floorf(x), fy = floorf(y), fz = floorf(z);
    int ib = ((int)fy * L + (int)fx) * L + (int)fz;
    float wx = x - fx, wy = y - fy, wz = z - fz;
    const __half2* p = v + ib;
    float2 q00 = __half22float2(__ldg(p));             // (x0,   y0)
    float2 q01 = __half22float2(__ldg(p + L));         // (x0+1, y0)
    float2 q10 = __half22float2(__ldg(p + LL2));       // (x0,   y0+1)
    float2 q11 = __half22float2(__ldg(p + LL2 + L));   // (x0+1, y0+1)
    float m00 = q00.x + wz * (q00.y - q00.x);
    float m01 = q01.x + wz * (q01.y - q01.x);
    float m10 = q10.x + wz * (q10.y - q10.x);
    float m11 = q11.x + wz * (q11.y - q11.x);
    float m0 = m00 + wx * (m01 - m00);
    float m1 = m10 + wx * (m11 - m10);
    return m0 + wy * (m1 - m0);
}

// warp-wide suffix (reverse inclusive) scan: s_l = sum_{m>=l} v_m
__device__ __forceinline__ float warp_suffix_scan(float s, int lane) {
    #pragma unroll
    for (int off = 1; off < 32; off <<= 1) {
        float t = __shfl_down_sync(0xffffffffu, s, off);
        if (lane < 32 - off) s += t;
    }
    return s;
}

// ---------- kernel P: build x-pair-packed bordered density ----------
// (round-7 proven form: 4 independent elements/thread, 7.8us measured)
__global__ void __launch_bounds__(256) kP(const float* __restrict__ d) {
    int i0 = (blockIdx.x * 256 + threadIdx.x) * 4;
    #pragma unroll
    for (int k = 0; k < 4; ++k) {
        int i = i0 + k;
        if (i < SV) {
            int z = i / SS;
            int r = i - z * SS;
            int y = r / S;
            int x = r - y * S;
            float v  = __ldg(d + i);
            float vn = (x + 1 < S) ? __ldg(d + i + 1) : 0.f;
            int base = (z + 1) * PP + (y + 1) * P;
            g_pd2[base + x + 1] = make_float2(v, vn);
            if (x == 0) g_pd2[base] = make_float2(0.f, v);   // left-border pair
        }
    }
}

// ---------- kernel A: rotate + suffix-cumsum + exp, one WARP per column ----------
// blockIdx.y selects the light (both lights in one launch: halves wave tail).
// Slab-culled; writes (e[z], e[z+1]) pairs; boundary above topmost chunk = 1.
__global__ void __launch_bounds__(128) kA(Mat3 R0, Mat3 R1) {
    int warp = threadIdx.x >> 5, lane = threadIdx.x & 31;
    int t = blockIdx.x * 4 + warp;               // column id, exact (12544*4 = L^2)
    const Mat3 R = blockIdx.y ? R1 : R0;
    __half2* __restrict__ up = g_upb[blockIdx.y];
    int x = t % L, y = t / L;
    float bx = -1.f + 2.f * (float)x / 223.f;
    float by = -1.f + 2.f * (float)y / 223.f;
    float A0 = 111.5f * (R.m[0] * bx + R.m[1] * by + 1.f - R.m[2]) - (float)OFF;
    float A1 = 111.5f * (R.m[3] * bx + R.m[4] * by + 1.f - R.m[5]) - (float)OFF;
    float A2 = 111.5f * (R.m[6] * bx + R.m[7] * by + 1.f - R.m[8]) - (float)OFF;
    float D0 = R.m[2], D1 = R.m[5], D2 = R.m[8];

    // slab intersection vs expanded bounds (-3, S+2); warp-uniform.
    const float lob = -3.f, hib = (float)S + 2.f;
    float t0 = 0.f, t1 = 223.f;
    {
        float A[3] = {A0, A1, A2}, D[3] = {D0, D1, D2};
        #pragma unroll
        for (int k = 0; k < 3; ++k) {
            if (fabsf(D[k]) < 1e-6f) {
                if (A[k] <= lob || A[k] >= hib) t1 = -1.e9f;
            } else {
                float u = __fdividef(lob - A[k], D[k]);
                float v = __fdividef(hib - A[k], D[k]);
                t0 = fmaxf(t0, fminf(u, v));
                t1 = fminf(t1, fmaxf(u, v));
            }
        }
    }
    if (t1 < t0) return;                         // column never touched by kBC
    int c0 = max(0, (int)floorf((t0 - 3.f) * 0.03125f));
    int c1 = min(6, (int)floorf((t1 + 3.f) * 0.03125f));

    float carry = 0.f;
    float prev_e = 1.f;                          // value at z = 32*c1 + 32
    __half2* __restrict__ col = up + (size_t)t * L;
    for (int cc = c1; cc >= c0; --cc) {          // march high z -> low z
        int zb = cc * 32;
        float zf = (float)(zb + lane);
        float px = fmaf(zf, D0, A0);
        float py = fmaf(zf, D1, A1);
        float pz = fmaf(zf, D2, A2);
        bool inb = (px > -1.f) && (px < (float)S) &&
                   (py > -1.f) && (py < (float)S) &&
                   (pz > -1.f) && (pz < (float)S);
        unsigned b = __ballot_sync(0xffffffffu, inb);
        float e;
        if (b == 0) {
            e = __expf(-CABS * carry);
        } else {
            float dv = inb ? triS_f2(g_pd2, px, py, pz) : 0.f;
            float s = warp_suffix_scan(dv, lane);
            e = __expf(-CABS * (carry + s));
            carry += __shfl_sync(0xffffffffu, s, 0);
        }
        float e_next = __shfl_down_sync(0xffffffffu, e, 1);
        if (lane == 31) e_next = prev_e;
        col[zb + lane] = __floats2half2_rn(e, e_next);
        prev_e = __shfl_sync(0xffffffffu, e, 0);
    }
}

// ---------- kernel BC: back-rotate both lights + composite, one WARP per pixel ----------
__global__ void __launch_bounds__(128) kBC(const float* __restrict__ d,
                                           Mat3 R0, Mat3 R1,
                                           float* __restrict__ out) {
    __shared__ float sd[160 * 4];                // sd[(z+31)*4 + pixel], z in [-31,128]
    int tid = threadIdx.x;
    int warp = tid >> 5, lane = tid & 31;
    int t0 = blockIdx.x * 4;
    #pragma unroll
    for (int k = tid; k < 160 * 4; k += 128) sd[k] = 0.f;
    __syncthreads();
    for (int k = tid; k < S * 4; k += 128) {     // coalesced staging of d columns
        int z = k >> 2, j = k & 3;
        int t = t0 + j;
        if (t < SS) sd[(z + 31) * 4 + j] = __ldg(d + (size_t)z * SS + t);
    }
    __syncthreads();

    int t = t0 + warp;                           // this warp's pixel
    int x = t % S, y = t / S;
    const __half2* __restrict__ up0 = g_upb[0];
    const __half2* __restrict__ up1 = g_upb[1];
    float bx = -1.f + 2.f * (float)(x + OFF) / 223.f;
    float by = -1.f + 2.f * (float)(y + OFF) / 223.f;
    float bz0 = -1.f + 2.f * (float)OFF / 223.f;
    float B00 = 111.5f * (R0.m[0] * bx + R0.m[3] * by + R0.m[6] * bz0 + 1.f);
    float B01 = 111.5f * (R0.m[1] * bx + R0.m[4] * by + R0.m[7] * bz0 + 1.f);
    float B02 = 111.5f * (R0.m[2] * bx + R0.m[5] * by + R0.m[8] * bz0 + 1.f);
    float B10 = 111.5f * (R1.m[0] * bx + R1.m[3] * by + R1.m[6] * bz0 + 1.f);
    float B11 = 111.5f * (R1.m[1] * bx + R1.m[4] * by + R1.m[7] * bz0 + 1.f);
    float B12 = 111.5f * (R1.m[2] * bx + R1.m[5] * by + R1.m[8] * bz0 + 1.f);
    float carry = 0.f, a0 = 0.f, a1 = 0.f, a2 = 0.f;
    const float c227 = 227.f / 255.f, c69 = 69.f / 255.f, c25 = 25.f / 255.f, c66 = 66.f / 255.f;
    #pragma unroll
    for (int c = 0; c < 5; ++c) {
        int z = (97 - 32 * c) + lane;            // bases 97,65,33,1,-31 cover 0..128
        float dv = sd[(z + 31) * 4 + warp];      // 0 for z<0 / tail pixels
        float comb0 = 0.f, comb1 = 0.f, comb2 = 0.f;
        if (z >= 0) {
            float zf = (float)z;
            float s0 = triLT_h2(up0, fmaf(zf, R0.m[6], B00),
                                     fmaf(zf, R0.m[7], B01),
                                     fmaf(zf, R0.m[8], B02));
            float s1 = triLT_h2(up1, fmaf(zf, R1.m[6], B10),
                                     fmaf(zf, R1.m[7], B11),
                                     fmaf(zf, R1.m[8], B12));
            comb0 = s0        + s1 * c227;
            comb1 = s0 * c69  + s1;
            comb2 = s0 * c25  + s1 * c66;
        }
        float s = warp_suffix_scan(dv, lane);
        float tr = __expf(-CABS * (carry + s));
        float w = dv * tr;
        a0 = fmaf(w, comb0, a0);
        a1 = fmaf(w, comb1, a1);
        a2 = fmaf(w, comb2, a2);
        carry += __shfl_sync(0xffffffffu, s, 0);
    }
    #pragma unroll
    for (int off = 16; off; off >>= 1) {
        a0 += __shfl_xor_sync(0xffffffffu, a0, off);
        a1 += __shfl_xor_sync(0xffffffffu, a1, off);
        a2 += __shfl_xor_sync(0xffffffffu, a2, off);
    }
    if (lane == 0 && t < SS) {
        out[t]          = fminf(fmaxf(CABS * a0, 0.f), 1.f);
        out[SS + t]     = fminf(fmaxf(CABS * a1, 0.f), 1.f);
        out[2 * SS + t] = fminf(fmaxf(CABS * a2, 0.f), 1.f);
    }
}

// ---------- host ----------

static void light_matrix(double lx, double ly, double lz, Mat3* Rf) {
    double n = sqrt(lx * lx + ly * ly + lz * lz);
    double ldx = lx / n, ldy = ly / n, ldz = lz / n;
    double yw = -asin(ldx);
    if (ldz < 0) yw = -M_PI - yw;
    double p = asin(ldy);
    double cy = cos(yw), sy = sin(yw), cp = cos(p), sp = sin(p);
    // R = Ry @ Rp
    double R[9] = { cy,  sy * sp,  sy * cp,
                    0.0, cp,      -sp,
                   -sy,  cy * sp,  cy * cp };
    for (int i = 0; i < 9; i++) Rf->m[i] = (float)R[i];
}

extern "C" void kernel_launch(void* const* d_in, const int* in_sizes, int n_in,
                              void* d_out, int out_size) {
    const float* d = (const float*)d_in[0];
    float* out = (float*)d_out;

    Mat3 R0, R1;
    light_matrix(2.0, 1.0, 1.0, &R0);
    light_matrix(-1.0, 0.5, 0.0, &R1);

    kP<<<(SV + 1023) / 1024, 256>>>(d);
    dim3 gridA(LL2 / 4, 2, 1);                   // both lights in one launch
    kA<<<gridA, 128>>>(R0, R1);
    kBC<<<(SS + 3) / 4, 128>>>(d, R0, R1, out);
}